// round 12
// baseline (speedup 1.0000x reference)
#include <cuda_runtime.h>
#include <cuda_bf16.h>

#define BATCH 64
#define CHANS 3
#define HH 384
#define WW 384
#define HW (HH * WW)
#define HALF (HW / 2)   // 73728: one thread handles one column in an adjacent-row pair

__global__ __launch_bounds__(256, 5)
void affine_kernel(const float* __restrict__ imgs,
                   const float* __restrict__ theta,
                   float* __restrict__ out) {
    // pix indexes (row-pair, col): rp in [0,192), col in [0,384)
    const int pix = blockIdx.x * blockDim.x + threadIdx.x;   // < HALF, exact
    const int b = blockIdx.y;
    const int rp  = pix / WW;
    const int col = pix - rp * WW;
    const int row = rp * 2;

    const float* th = theta + b * 6;
    const float t00 = __ldg(th + 0);
    const float t01 = __ldg(th + 1);
    const float t02 = __ldg(th + 2);
    const float t10 = __ldg(th + 3);
    const float t11 = __ldg(th + 4);
    const float t12 = __ldg(th + 5);

    const float xc = (float)col - 191.5f;
    const float yc = (float)row - 191.5f;
    // pixel A = (row, col), pixel B = (row+1, col)
    const float ixA = fmaf(t00, xc, fmaf(t01, yc, t02 + 191.5f));
    const float iyA = fmaf(t10, xc, fmaf(t11, yc, t12 + 191.5f));
    const float ixB = ixA + t01;
    const float iyB = iyA + t11;

    const int x0A = __float2int_rd(ixA);
    const int y0A = __float2int_rd(iyA);
    const int x0B = __float2int_rd(ixB);
    const int y0B = __float2int_rd(iyB);

    const float wx1A = ixA - (float)x0A, wy1A = iyA - (float)y0A;
    const float wx1B = ixB - (float)x0B, wy1B = iyB - (float)y0B;
    const float wx0A = 1.0f - wx1A, wy0A = 1.0f - wy1A;
    const float wx0B = 1.0f - wx1B, wy0B = 1.0f - wy1B;

    float w00A = wx0A * wy0A, w10A = wx1A * wy0A, w01A = wx0A * wy1A, w11A = wx1A * wy1A;
    float w00B = wx0B * wy0B, w10B = wx1B * wy0B, w01B = wx0B * wy1B, w11B = wx1B * wy1B;

    const float* img = imgs + (size_t)b * (CHANS * HW);
    float* opA = out + (size_t)b * (CHANS * HW) + row * WW + col;
    float* opB = opA + WW;

    const bool intA = ((unsigned)x0A < (unsigned)(WW - 1)) & ((unsigned)y0A < (unsigned)(HH - 1));
    const bool intB = ((unsigned)x0B < (unsigned)(WW - 1)) & ((unsigned)y0B < (unsigned)(HH - 1));

    if (__all_sync(0xFFFFFFFFu, intA & intB)) {
        // fast path: one base reg per pixel, 24 LDGs batched (imm offsets) -> MLP=24
        const float* pA = img + y0A * WW + x0A;
        const float* pB = img + y0B * WW + x0B;

        float a00[CHANS], a10[CHANS], a01[CHANS], a11[CHANS];
        float b00[CHANS], b10[CHANS], b01[CHANS], b11[CHANS];
#pragma unroll
        for (int c = 0; c < CHANS; c++) {
            const float* pa = pA + c * HW;
            const float* pb = pB + c * HW;
            a00[c] = __ldg(pa);
            a10[c] = __ldg(pa + 1);
            a01[c] = __ldg(pa + WW);
            a11[c] = __ldg(pa + WW + 1);
            b00[c] = __ldg(pb);
            b10[c] = __ldg(pb + 1);
            b01[c] = __ldg(pb + WW);
            b11[c] = __ldg(pb + WW + 1);
        }
#pragma unroll
        for (int c = 0; c < CHANS; c++) {
            float accA = a00[c] * w00A;
            accA = fmaf(a10[c], w10A, accA);
            accA = fmaf(a01[c], w01A, accA);
            accA = fmaf(a11[c], w11A, accA);
            __stcs(opA + c * HW, accA);          // streaming store: don't pollute L2
            float accB = b00[c] * w00B;
            accB = fmaf(b10[c], w10B, accB);
            accB = fmaf(b01[c], w01B, accB);
            accB = fmaf(b11[c], w11B, accB);
            __stcs(opB + c * HW, accB);
        }
    } else {
        // generic path: clamp + validity-in-weights, both pixels
        const int x1A = x0A + 1, y1A = y0A + 1;
        const int x1B = x0B + 1, y1B = y0B + 1;

        const float vAx0 = ((unsigned)x0A < (unsigned)WW) ? 1.0f : 0.0f;
        const float vAx1 = ((unsigned)x1A < (unsigned)WW) ? 1.0f : 0.0f;
        const float vAy0 = ((unsigned)y0A < (unsigned)HH) ? 1.0f : 0.0f;
        const float vAy1 = ((unsigned)y1A < (unsigned)HH) ? 1.0f : 0.0f;
        const float vBx0 = ((unsigned)x0B < (unsigned)WW) ? 1.0f : 0.0f;
        const float vBx1 = ((unsigned)x1B < (unsigned)WW) ? 1.0f : 0.0f;
        const float vBy0 = ((unsigned)y0B < (unsigned)HH) ? 1.0f : 0.0f;
        const float vBy1 = ((unsigned)y1B < (unsigned)HH) ? 1.0f : 0.0f;

        w00A *= vAx0 * vAy0; w10A *= vAx1 * vAy0; w01A *= vAx0 * vAy1; w11A *= vAx1 * vAy1;
        w00B *= vBx0 * vBy0; w10B *= vBx1 * vBy0; w01B *= vBx0 * vBy1; w11B *= vBx1 * vBy1;

        const int x0Ac = min(max(x0A, 0), WW - 1), x1Ac = min(max(x1A, 0), WW - 1);
        const int y0Ac = min(max(y0A, 0), HH - 1), y1Ac = min(max(y1A, 0), HH - 1);
        const int x0Bc = min(max(x0B, 0), WW - 1), x1Bc = min(max(x1B, 0), WW - 1);
        const int y0Bc = min(max(y0B, 0), HH - 1), y1Bc = min(max(y1B, 0), HH - 1);

        const int oA00 = y0Ac * WW + x0Ac, oA10 = y0Ac * WW + x1Ac;
        const int oA01 = y1Ac * WW + x0Ac, oA11 = y1Ac * WW + x1Ac;
        const int oB00 = y0Bc * WW + x0Bc, oB10 = y0Bc * WW + x1Bc;
        const int oB01 = y1Bc * WW + x0Bc, oB11 = y1Bc * WW + x1Bc;

        float a00[CHANS], a10[CHANS], a01[CHANS], a11[CHANS];
        float b00[CHANS], b10[CHANS], b01[CHANS], b11[CHANS];
#pragma unroll
        for (int c = 0; c < CHANS; c++) {
            const float* pc = img + c * HW;
            a00[c] = __ldg(pc + oA00);
            a10[c] = __ldg(pc + oA10);
            a01[c] = __ldg(pc + oA01);
            a11[c] = __ldg(pc + oA11);
            b00[c] = __ldg(pc + oB00);
            b10[c] = __ldg(pc + oB10);
            b01[c] = __ldg(pc + oB01);
            b11[c] = __ldg(pc + oB11);
        }
#pragma unroll
        for (int c = 0; c < CHANS; c++) {
            float accA = a00[c] * w00A;
            accA = fmaf(a10[c], w10A, accA);
            accA = fmaf(a01[c], w01A, accA);
            accA = fmaf(a11[c], w11A, accA);
            __stcs(opA + c * HW, accA);
            float accB = b00[c] * w00B;
            accB = fmaf(b10[c], w10B, accB);
            accB = fmaf(b01[c], w01B, accB);
            accB = fmaf(b11[c], w11B, accB);
            __stcs(opB + c * HW, accB);
        }
    }
}

extern "C" void kernel_launch(void* const* d_in, const int* in_sizes, int n_in,
                              void* d_out, int out_size) {
    const float* imgs  = (const float*)d_in[0];
    const float* theta = (const float*)d_in[1];
    float* out = (float*)d_out;

    dim3 block(256);
    dim3 grid(HALF / 256, BATCH);   // 288 x 64
    affine_kernel<<<grid, block>>>(imgs, theta, out);
}